// round 6
// baseline (speedup 1.0000x reference)
#include <cuda_runtime.h>

#define BB 8
#define CC 64
#define WH 214272             // 496*432
#define WH4 53568             // WH/4
#define WH32 6696             // WH/32
#define CHUNKS 1674           // WH/128 chunks per batch
#define BLOCKS_PER_BATCH 837  // WH / 256
#define NBLOCKS (BB * BLOCKS_PER_BATCH)
#define EPSF 0.001f

// Scratch (device globals — no allocations allowed).
// Zero-initialized at module load; finalize tail resets counters so every
// graph replay starts clean.
__device__ float        g_S1[CC];
__device__ float        g_S2[CC];
__device__ int          g_n[BB];
__device__ float        g_inv[CC];
__device__ unsigned int g_maskbits[BB * WH32];      // 1 bit / position (214 KB)
__device__ unsigned int g_cbase[BB * CHUNKS];       // compact base per chunk
__device__ float        g_compact[27426816];        // capacity = 25% density * 64ch (~110 MB)
__device__ unsigned int g_alloc;
__device__ unsigned int g_done;

// ---------------------------------------------------------------------------
// Pass 1: per-channel sums + nonzero count + mask bitmap + COMPACTION.
// Unmasked positions are exactly zero in every channel (x = normal*occ), so
// plain sums equal masked sums, and the compact buffer holds every value the
// normalize pass will ever need. Per 128-position chunk, nonzero positions'
// 64-channel vectors are stored channel-major at an atomically allocated base
// (base recorded in g_cbase -> output independent of atomic order).
// Last block runs finalize inline.
// ---------------------------------------------------------------------------
__global__ void __launch_bounds__(256) stats_kernel(const float* __restrict__ x) {
    const int tid  = threadIdx.x;
    const int b    = blockIdx.x / BLOCKS_PER_BATCH;
    const int blockInBatch = blockIdx.x % BLOCKS_PER_BATCH;
    const int pos  = blockInBatch * 256 + tid;
    const float* xb = x + (size_t)b * CC * WH + pos;

    float v[CC];
    float csum = 0.0f;
#pragma unroll
    for (int c = 0; c < CC; c++) {
        v[c] = __ldcs(&xb[(size_t)c * WH]);
        csum += v[c];
    }
    const bool m = (csum != 0.0f);

    const int warp = tid >> 5;
    const int lane = tid & 31;

    __shared__ float    sm[128 * 65];   // transpose buffer (padded)
    __shared__ float    r1[256];
    __shared__ float    r2[256];
    __shared__ int      sCnt[8];        // per-warp popc
    __shared__ unsigned sW[8];          // per-warp ballot
    __shared__ int      sWPref[8];      // warp prefix within its chunk
    __shared__ int      sCc[2];         // per-chunk counts
    __shared__ unsigned sBaseS[2];      // per-chunk compact bases
    __shared__ int      posList[128];   // rank -> local position (per phase)

    unsigned ballot = __ballot_sync(0xffffffffu, m);
    if (lane == 0) {
        sCnt[warp] = __popc(ballot);
        sW[warp]   = ballot;
        g_maskbits[b * WH32 + (pos >> 5)] = ballot;
    }
    __syncthreads();

    if (tid < 8) {                      // warp prefix within chunk (4 warps/chunk)
        int j = tid & 3, b4 = tid & ~3;
        int p = 0;
        for (int q = 0; q < j; q++) p += sCnt[b4 + q];
        sWPref[tid] = p;
    }
    if (tid < 2)
        sCc[tid] = sCnt[4*tid] + sCnt[4*tid+1] + sCnt[4*tid+2] + sCnt[4*tid+3];
    __syncthreads();

    if (tid == 0) {
        unsigned tot = (unsigned)(sCc[0] + sCc[1]);
        unsigned base0 = atomicAdd(&g_alloc, tot);
        sBaseS[0] = base0;
        sBaseS[1] = base0 + (unsigned)sCc[0];
        g_cbase[b * CHUNKS + blockInBatch * 2]     = base0;
        g_cbase[b * CHUNKS + blockInBatch * 2 + 1] = base0 + (unsigned)sCc[0];
    }
    __syncthreads();

    const int c = tid & 63;             // channel this thread reduces
    const int g = tid >> 6;             // position group (4 groups x 32 pos)
    float a1 = 0.0f, a2 = 0.0f;

#pragma unroll
    for (int phase = 0; phase < 2; phase++) {
        if ((tid >> 7) == phase) {
            const int row = tid & 127;
#pragma unroll
            for (int cc = 0; cc < CC; cc++) sm[row * 65 + cc] = v[cc];
        }
        if (tid < 128) {                // build rank -> position list for this chunk
            unsigned w = sW[phase * 4 + (tid >> 5)];
            unsigned bit = tid & 31;
            if ((w >> bit) & 1u) {
                int rank = sWPref[phase * 4 + (tid >> 5)]
                         + __popc(w & ((1u << bit) - 1u));
                posList[rank] = tid;
            }
        }
        __syncthreads();
        // per-channel reduction over this half
#pragma unroll
        for (int i = 0; i < 32; i++) {
            float val = sm[(g * 32 + i) * 65 + c];
            a1 += val;
            a2 += val * val;
        }
        // compact store: channel-major [c][rank] at this chunk's base
        {
            const int cntp = sCc[phase];
            const int E = cntp * CC;
            const size_t gb = (size_t)sBaseS[phase] * CC;
            for (int i = tid; i < E; i += 256) {
                int cc = i / cntp;
                int r  = i - cc * cntp;
                __stcs(&g_compact[gb + i], sm[posList[r] * 65 + cc]);
            }
        }
        __syncthreads();
    }

    r1[tid] = a1;
    r2[tid] = a2;
    __syncthreads();

    if (tid < CC) {
        float s1 = r1[tid] + r1[tid + 64] + r1[tid + 128] + r1[tid + 192];
        float s2 = r2[tid] + r2[tid + 64] + r2[tid + 128] + r2[tid + 192];
        atomicAdd(&g_S1[tid], s1);
        atomicAdd(&g_S2[tid], s2);
    }
    if (tid == 0) {
        int cn = 0;
#pragma unroll
        for (int w = 0; w < 8; w++) cn += sCnt[w];
        atomicAdd(&g_n[b], cn);
    }

    // ---- merged finalize: last block computes inv + resets state -----------
    __shared__ bool isLast;
    __shared__ int  spad[BB];
    __shared__ int  sN;
    __threadfence();
    if (tid == 0) {
        unsigned int d = atomicAdd(&g_done, 1u);
        isLast = (d == (unsigned int)(NBLOCKS - 1));
    }
    __syncthreads();
    if (!isLast) return;

    if (tid == 0) {
        g_done = 0;
        g_alloc = 0;
        int mx = 0;
#pragma unroll
        for (int bb = 0; bb < BB; bb++) mx = max(mx, g_n[bb]);
        sN = mx;
#pragma unroll
        for (int bb = 0; bb < BB; bb++) {
            spad[bb] = mx - g_n[bb];
            g_n[bb] = 0;
        }
    }
    __syncthreads();
    if (tid < CC) {
        float s1 = g_S1[tid];
        float s2 = g_S2[tid];
#pragma unroll
        for (int bb = 0; bb < BB; bb++) {
            float x00 = x[(size_t)bb * CC * WH + (size_t)tid * WH];
            float p = (float)spad[bb];
            s1 += p * x00;
            s2 += p * x00 * x00;
        }
        float count = (float)BB * (float)sN;
        float mean = s1 / count;
        float var  = s2 / count - mean * mean;
        g_inv[tid] = rsqrtf(var + EPSF);
        g_S1[tid] = 0.0f;
        g_S2[tid] = 0.0f;
    }
}

// ---------------------------------------------------------------------------
// Pass 2: normalize WITHOUT reading x. Zeros everywhere except nonzero
// positions, whose values come from the compact buffer (dense, coalesced).
// Block = 1024 positions (8 chunks) of one (b,c) plane.
// ---------------------------------------------------------------------------
__global__ void __launch_bounds__(256) norm_kernel(float* __restrict__ out) {
    const unsigned int bc = blockIdx.y;       // b*64 + c
    const unsigned int b  = bc >> 6;
    const unsigned int c  = bc & 63u;
    const int t = threadIdx.x;
    const unsigned int s0 = blockIdx.x * 1024u;   // first position of block

    __shared__ unsigned sWords[32];
    __shared__ int      sPc[32];
    __shared__ int      sPref[32];   // word prefix within chunk
    __shared__ int      sCk[8];      // chunk counts
    __shared__ unsigned sBase[8];    // chunk compact bases

    if (t < 32) {
        unsigned widx = (s0 >> 5) + t;
        unsigned w = (widx < WH32) ? g_maskbits[b * WH32 + widx] : 0u;
        sWords[t] = w;
        sPc[t] = __popc(w);
    }
    __syncthreads();
    if (t < 32) {
        int j = t & 3, b4 = t & ~3;
        int p = 0;
        for (int q = 0; q < j; q++) p += sPc[b4 + q];
        sPref[t] = p;
    }
    if (t < 8) {
        sCk[t] = sPc[4*t] + sPc[4*t+1] + sPc[4*t+2] + sPc[4*t+3];
        unsigned ch = (s0 >> 7) + t;
        sBase[t] = (ch < CHUNKS) ? g_cbase[b * CHUNKS + ch] : 0u;
    }
    __syncthreads();

    const unsigned int p4 = blockIdx.x * 256u + t;
    if (p4 >= WH4) return;

    const int lp   = t * 4;          // position within block
    const int k    = lp >> 7;        // chunk within block
    const int widx = lp >> 5;
    const unsigned w = sWords[widx];
    const int bit0 = lp & 31;
    int rank = sPref[widx] + __popc(w & ((1u << bit0) - 1u));
    const int cnt = sCk[k];
    const float inv = g_inv[c];
    const float* cb = g_compact + (size_t)sBase[k] * CC + (size_t)c * cnt;

    float4 o = make_float4(0.0f, 0.0f, 0.0f, 0.0f);
    if ((w >> bit0)       & 1u) { o.x = __ldcs(cb + rank) * inv; rank++; }
    if ((w >> (bit0 + 1)) & 1u) { o.y = __ldcs(cb + rank) * inv; rank++; }
    if ((w >> (bit0 + 2)) & 1u) { o.z = __ldcs(cb + rank) * inv; rank++; }
    if ((w >> (bit0 + 3)) & 1u) { o.w = __ldcs(cb + rank) * inv; }

    __stcs(reinterpret_cast<float4*>(out) + ((size_t)bc * WH4 + p4), o);
}

// ---------------------------------------------------------------------------
extern "C" void kernel_launch(void* const* d_in, const int* in_sizes, int n_in,
                              void* d_out, int out_size) {
    const float* x = (const float*)d_in[0];
    float* out = (float*)d_out;

    stats_kernel<<<NBLOCKS, 256>>>(x);
    dim3 ngrid((WH4 + 255) / 256, BB * CC);   // (210, 512)
    norm_kernel<<<ngrid, 256>>>(out);
}

// round 7
// speedup vs baseline: 1.3945x; 1.3945x over previous
#include <cuda_runtime.h>

#define BB 8
#define CC 64
#define WH 214272             // 496*432
#define WH4 53568             // WH/4
#define WH32 6696             // WH/32
#define CHUNKS 1674           // WH/128 chunks per batch
#define BLOCKS_PER_BATCH 837  // WH / 256
#define NBLOCKS (BB * BLOCKS_PER_BATCH)
#define EPSF 0.001f

// Scratch (device globals — no allocations allowed).
__device__ float        g_S1[CC];
__device__ float        g_S2[CC];
__device__ int          g_n[BB];
__device__ float        g_inv[CC];
__device__ unsigned int g_maskbits[BB * WH32];      // 1 bit / position (214 KB)
__device__ unsigned int g_cbase[BB * CHUNKS];       // compact base (in positions) per chunk
__device__ float        g_compact[27426816];        // 25% density capacity (~110 MB)
__device__ unsigned int g_alloc;
__device__ unsigned int g_done;

// ---------------------------------------------------------------------------
// Pass 1: per-channel sums + nonzero count + mask bitmap + compaction.
// Compact layout is POSITION-MAJOR: each nonzero position's 64-channel vector
// is contiguous (256B). Store index math is shift/and only (no runtime IDIV).
// Last block runs finalize inline.
// ---------------------------------------------------------------------------
__global__ void __launch_bounds__(256) stats_kernel(const float* __restrict__ x) {
    const int tid  = threadIdx.x;
    const int b    = blockIdx.x / BLOCKS_PER_BATCH;
    const int blockInBatch = blockIdx.x % BLOCKS_PER_BATCH;
    const int pos  = blockInBatch * 256 + tid;
    const float* xb = x + (size_t)b * CC * WH + pos;

    float v[CC];
    float csum = 0.0f;
#pragma unroll
    for (int c = 0; c < CC; c++) {
        v[c] = __ldcs(&xb[(size_t)c * WH]);
        csum += v[c];
    }
    const bool m = (csum != 0.0f);

    const int warp = tid >> 5;
    const int lane = tid & 31;

    __shared__ float    sm[128 * 65];   // transpose buffer (padded)
    __shared__ float    r1[256];
    __shared__ float    r2[256];
    __shared__ int      sCnt[8];        // per-warp popc
    __shared__ unsigned sW[8];          // per-warp ballot
    __shared__ int      sWPref[8];      // warp prefix within its chunk
    __shared__ int      sCc[2];         // per-chunk counts
    __shared__ unsigned sBaseS[2];      // per-chunk compact bases
    __shared__ int      posList[128];   // rank -> local position (per phase)

    unsigned ballot = __ballot_sync(0xffffffffu, m);
    if (lane == 0) {
        sCnt[warp] = __popc(ballot);
        sW[warp]   = ballot;
        g_maskbits[b * WH32 + (pos >> 5)] = ballot;
    }
    __syncthreads();

    if (tid < 8) {                      // warp prefix within chunk (4 warps/chunk)
        int j = tid & 3, b4 = tid & ~3;
        int p = 0;
        for (int q = 0; q < j; q++) p += sCnt[b4 + q];
        sWPref[tid] = p;
    }
    if (tid < 2)
        sCc[tid] = sCnt[4*tid] + sCnt[4*tid+1] + sCnt[4*tid+2] + sCnt[4*tid+3];
    __syncthreads();

    if (tid == 0) {
        unsigned tot = (unsigned)(sCc[0] + sCc[1]);
        unsigned base0 = atomicAdd(&g_alloc, tot);
        sBaseS[0] = base0;
        sBaseS[1] = base0 + (unsigned)sCc[0];
        g_cbase[b * CHUNKS + blockInBatch * 2]     = base0;
        g_cbase[b * CHUNKS + blockInBatch * 2 + 1] = base0 + (unsigned)sCc[0];
    }
    __syncthreads();

    const int c = tid & 63;             // channel this thread reduces
    const int g = tid >> 6;             // position group (4 groups x 32 pos)
    float a1 = 0.0f, a2 = 0.0f;

#pragma unroll
    for (int phase = 0; phase < 2; phase++) {
        if ((tid >> 7) == phase) {
            const int row = tid & 127;
#pragma unroll
            for (int cc = 0; cc < CC; cc++) sm[row * 65 + cc] = v[cc];
        }
        if (tid < 128) {                // rank -> position list for this chunk
            unsigned w = sW[phase * 4 + (tid >> 5)];
            unsigned bit = tid & 31;
            if ((w >> bit) & 1u) {
                int rank = sWPref[phase * 4 + (tid >> 5)]
                         + __popc(w & ((1u << bit) - 1u));
                posList[rank] = tid;
            }
        }
        __syncthreads();
        // per-channel reduction over this half
#pragma unroll
        for (int i = 0; i < 32; i++) {
            float val = sm[(g * 32 + i) * 65 + c];
            a1 += val;
            a2 += val * val;
        }
        // compact store, position-major: element i -> rank i>>6, channel i&63
        {
            const int E = sCc[phase] * CC;
            const size_t gb = (size_t)sBaseS[phase] * CC;
            for (int i = tid; i < E; i += 256)
                __stcs(&g_compact[gb + i], sm[posList[i >> 6] * 65 + (i & 63)]);
        }
        __syncthreads();
    }

    r1[tid] = a1;
    r2[tid] = a2;
    __syncthreads();

    if (tid < CC) {
        float s1 = r1[tid] + r1[tid + 64] + r1[tid + 128] + r1[tid + 192];
        float s2 = r2[tid] + r2[tid + 64] + r2[tid + 128] + r2[tid + 192];
        atomicAdd(&g_S1[tid], s1);
        atomicAdd(&g_S2[tid], s2);
    }
    if (tid == 0) {
        int cn = 0;
#pragma unroll
        for (int w = 0; w < 8; w++) cn += sCnt[w];
        atomicAdd(&g_n[b], cn);
    }

    // ---- merged finalize: last block computes inv + resets state -----------
    __shared__ bool isLast;
    __shared__ int  spad[BB];
    __shared__ int  sN;
    __threadfence();
    if (tid == 0) {
        unsigned int d = atomicAdd(&g_done, 1u);
        isLast = (d == (unsigned int)(NBLOCKS - 1));
    }
    __syncthreads();
    if (!isLast) return;

    if (tid == 0) {
        g_done = 0;
        g_alloc = 0;
        int mx = 0;
#pragma unroll
        for (int bb = 0; bb < BB; bb++) mx = max(mx, g_n[bb]);
        sN = mx;
#pragma unroll
        for (int bb = 0; bb < BB; bb++) {
            spad[bb] = mx - g_n[bb];
            g_n[bb] = 0;
        }
    }
    __syncthreads();
    if (tid < CC) {
        float s1 = g_S1[tid];
        float s2 = g_S2[tid];
#pragma unroll
        for (int bb = 0; bb < BB; bb++) {
            float x00 = x[(size_t)bb * CC * WH + (size_t)tid * WH];
            float p = (float)spad[bb];
            s1 += p * x00;
            s2 += p * x00 * x00;
        }
        float count = (float)BB * (float)sN;
        float mean = s1 / count;
        float var  = s2 / count - mean * mean;
        g_inv[tid] = rsqrtf(var + EPSF);
        g_S1[tid] = 0.0f;
        g_S2[tid] = 0.0f;
    }
}

// ---------------------------------------------------------------------------
// Pass 2: normalize WITHOUT reading x. One block per 128-position chunk:
// densely load that chunk's compact values into smem (coalesced), build a
// uchar rank table, then emit the 128x64 dense tile (zeros elsewhere) with
// LDS + FMUL + coalesced float4 stores. Each warp writes one channel's
// contiguous 512B run per iteration.
// ---------------------------------------------------------------------------
__global__ void __launch_bounds__(256) norm_kernel(float* __restrict__ out) {
    const int b     = blockIdx.y;
    const int chunk = blockIdx.x;       // 0..1673
    const int t     = threadIdx.x;

    __shared__ unsigned      sW[4];
    __shared__ int           sPc[4];
    __shared__ int           sPref[4];
    __shared__ int           sCnt_;
    __shared__ unsigned      sBase_;
    __shared__ unsigned char sRank8[128];
    __shared__ float         sVal[128 * 65];   // worst-case cnt=128

    if (t < 4) {
        unsigned w = g_maskbits[b * WH32 + chunk * 4 + t];
        sW[t]  = w;
        sPc[t] = __popc(w);
    }
    __syncthreads();
    if (t == 0) {
        sPref[0] = 0;
        sPref[1] = sPc[0];
        sPref[2] = sPc[0] + sPc[1];
        sPref[3] = sPc[0] + sPc[1] + sPc[2];
        sCnt_  = sPref[3] + sPc[3];
        sBase_ = g_cbase[b * CHUNKS + chunk];
    }
    __syncthreads();
    if (t < 128) {
        unsigned w = sW[t >> 5];
        int bit = t & 31;
        sRank8[t] = (unsigned char)(sPref[t >> 5] + __popc(w & ((1u << bit) - 1u)));
    }
    {
        const int E = sCnt_ * CC;
        const size_t gb = (size_t)sBase_ * CC;
        for (int i = t; i < E; i += 256)
            sVal[(i >> 6) * 65 + (i & 63)] = __ldcs(&g_compact[gb + i]);
    }
    __syncthreads();

    // Emit: 2048 float4 per chunk, 8 iterations of 256 threads.
    // e = j*256+t: c = e>>5 (warp-uniform), p4 = e&31.
    const size_t outBase4 = ((size_t)b * CC * WH + (size_t)chunk * 128) >> 2;
#pragma unroll
    for (int j = 0; j < 8; j++) {
        const int e  = j * 256 + t;
        const int c  = e >> 5;
        const int p4 = e & 31;
        const int p  = p4 * 4;
        const unsigned w = sW[p >> 5];
        const int sh = p & 31;
        const float inv = g_inv[c];
        uchar4 rk = *reinterpret_cast<const uchar4*>(&sRank8[p]);

        float4 o = make_float4(0.0f, 0.0f, 0.0f, 0.0f);
        if ((w >> sh)       & 1u) o.x = sVal[rk.x * 65 + c] * inv;
        if ((w >> (sh + 1)) & 1u) o.y = sVal[rk.y * 65 + c] * inv;
        if ((w >> (sh + 2)) & 1u) o.z = sVal[rk.z * 65 + c] * inv;
        if ((w >> (sh + 3)) & 1u) o.w = sVal[rk.w * 65 + c] * inv;

        __stcs(reinterpret_cast<float4*>(out) + outBase4 + (size_t)c * WH4 + p4, o);
    }
}

// ---------------------------------------------------------------------------
extern "C" void kernel_launch(void* const* d_in, const int* in_sizes, int n_in,
                              void* d_out, int out_size) {
    const float* x = (const float*)d_in[0];
    float* out = (float*)d_out;

    stats_kernel<<<NBLOCKS, 256>>>(x);
    dim3 ngrid(CHUNKS, BB);               // (1674, 8)
    norm_kernel<<<ngrid, 256>>>(out);
}